// round 6
// baseline (speedup 1.0000x reference)
#include <cuda_runtime.h>

#define BB 4
#define NN 2048
#define NT 50
#define ND 4
#define ITILE 128
#define JTILE 256
#define NJT (NN / JTILE)   /* 8  */
#define NIT (NN / ITILE)   /* 16 */
#define APAD 51            /* padded row stride in float4 units (odd -> spreads f4 banks) */

// ---------------- device scratch (static: allocation-free) ----------------
__device__ float  g_mhat[NT];
__device__ float  g_omega[ND];
__device__ float  g_A[NT * NT * ND];     // softplus(alpha) [ti][tj][d], f4-friendly
__device__ float  g_Acol[NT * ND];       // sum_u A[u][k][d]
__device__ float  g_summhat;
__device__ float4 g_Ep[BB * NN];         // exp(+omega_d * t_j)
__device__ float4 g_EmW[BB * NN];        // omega_d * exp(-omega_d * t_i)
__device__ float  g_mu_i[BB * NN];       // mhat[type_i]
__device__ float  g_comp_i[BB * NN];     // per-event compensator term (masked)
__device__ float  g_partial[NJT][BB * NN];

__device__ __forceinline__ float sp(float x) {
    // softplus, numerically matching log1p(exp(x))
    return fmaxf(x, 0.0f) + log1pf(__expf(-fabsf(x)));
}

// ---------------- kernel 1: parameter transforms ----------------
__global__ void setup_kernel(const float* __restrict__ mu_p,
                             const float* __restrict__ alpha_p,
                             const float* __restrict__ beta_p) {
    int t = threadIdx.x;
    if (t < NT) g_mhat[t] = sp(mu_p[t]);
    if (t < ND) g_omega[t] = sp(beta_p[t]);
    for (int x = t; x < NT * NT * ND; x += blockDim.x) g_A[x] = sp(alpha_p[x]);
    __syncthreads();
    for (int x = t; x < NT * ND; x += blockDim.x) {
        int k = x / ND, d = x - k * ND;
        float s = 0.0f;
        for (int u = 0; u < NT; u++) s += g_A[(u * NT + k) * ND + d];
        g_Acol[x] = s;
    }
    if (t == 0) {
        float s = 0.0f;
        for (int u = 0; u < NT; u++) s += g_mhat[u];
        g_summhat = s;
    }
}

// ---------------- kernel 2: per-event precompute ----------------
__global__ void event_kernel(const float* __restrict__ times,
                             const int*   __restrict__ types,
                             const float* __restrict__ mask,
                             const float* __restrict__ t1) {
    int idx = blockIdx.x * blockDim.x + threadIdx.x;
    if (idx >= BB * NN) return;
    int b = idx / NN;
    float t = times[idx];
    int ty = types[idx];
    float o0 = g_omega[0], o1 = g_omega[1], o2 = g_omega[2], o3 = g_omega[3];
    g_Ep[idx]  = make_float4(__expf(o0 * t), __expf(o1 * t),
                             __expf(o2 * t), __expf(o3 * t));
    g_EmW[idx] = make_float4(o0 * __expf(-o0 * t), o1 * __expf(-o1 * t),
                             o2 * __expf(-o2 * t), o3 * __expf(-o3 * t));
    g_mu_i[idx] = g_mhat[ty];
    float dt1 = t1[b] - t;
    float c = g_Acol[ty * ND + 0] * (1.0f - __expf(-o0 * dt1))
            + g_Acol[ty * ND + 1] * (1.0f - __expf(-o1 * dt1))
            + g_Acol[ty * ND + 2] * (1.0f - __expf(-o2 * dt1))
            + g_Acol[ty * ND + 3] * (1.0f - __expf(-o3 * dt1));
    g_comp_i[idx] = c * mask[idx];
}

// ---------------- kernel 3: triangular pairwise excitation ----------------
__global__ void __launch_bounds__(ITILE) pair_kernel(const int* __restrict__ types) {
    __shared__ float4 A_sh[NT * APAD];
    __shared__ float4 ep_sh[JTILE];
    __shared__ int    ty_sh[JTILE];

    int b  = blockIdx.z;
    int i0 = blockIdx.x * ITILE;
    int j0 = blockIdx.y * JTILE;
    int i  = i0 + threadIdx.x;
    float* part = &g_partial[blockIdx.y][b * NN + i];

    if (j0 >= i0 + ITILE) {   // no j < i intersects this tile
        *part = 0.0f;
        return;
    }

    // cooperative load of A (as float4 per (ti,k)) with padded rows
    const float4* Ag = (const float4*)g_A;
    for (int x = threadIdx.x; x < NT * NT; x += ITILE) {
        int ti = x / NT, k = x - ti * NT;
        A_sh[ti * APAD + k] = Ag[x];
    }
    for (int x = threadIdx.x; x < JTILE; x += ITILE) {
        ep_sh[x] = g_Ep[b * NN + j0 + x];
        ty_sh[x] = types[b * NN + j0 + x];
    }
    __syncthreads();

    int ti = types[b * NN + i];
    const float4* Arow = &A_sh[ti * APAD];
    float ax = 0.f, ay = 0.f, az = 0.f, aw = 0.f;

    int jend = i - j0;                  // strict j < i
    if (jend > JTILE) jend = JTILE;

    #pragma unroll 4
    for (int jj = 0; jj < jend; jj++) {
        float4 a = Arow[ty_sh[jj]];     // per-lane gather (padded rows)
        float4 e = ep_sh[jj];           // warp-uniform broadcast
        ax += a.x * e.x;
        ay += a.y * e.y;
        az += a.z * e.z;
        aw += a.w * e.w;
    }

    float4 w = g_EmW[b * NN + i];
    *part = ax * w.x + ay * w.y + az * w.z + aw * w.w;
}

// ---------------- kernel 4: final reduction per batch ----------------
__global__ void reduce_kernel(const float* __restrict__ mask,
                              const float* __restrict__ t0,
                              const float* __restrict__ t1,
                              float* __restrict__ out) {
    int b = blockIdx.x;
    __shared__ float sll[256], scc[256];
    float ll = 0.f, cc = 0.f;
    for (int i = threadIdx.x; i < NN; i += 256) {
        int idx = b * NN + i;
        float r = g_mu_i[idx];
        #pragma unroll
        for (int jt = 0; jt < NJT; jt++) r += g_partial[jt][idx];
        ll += logf(r + 1e-8f) * mask[idx];
        cc += g_comp_i[idx];
    }
    sll[threadIdx.x] = ll;
    scc[threadIdx.x] = cc;
    __syncthreads();
    for (int s = 128; s > 0; s >>= 1) {
        if (threadIdx.x < s) {
            sll[threadIdx.x] += sll[threadIdx.x + s];
            scc[threadIdx.x] += scc[threadIdx.x + s];
        }
        __syncthreads();
    }
    if (threadIdx.x == 0) {
        out[b]      = sll[0];
        out[BB + b] = (t1[b] - t0[b]) * g_summhat + scc[0];
    }
}

// ---------------- launch ----------------
extern "C" void kernel_launch(void* const* d_in, const int* in_sizes, int n_in,
                              void* d_out, int out_size) {
    const float* times   = (const float*)d_in[0];
    const int*   types   = (const int*)  d_in[1];
    const float* mask    = (const float*)d_in[2];
    const float* t0      = (const float*)d_in[3];
    const float* t1      = (const float*)d_in[4];
    const float* mu_p    = (const float*)d_in[5];
    const float* alpha_p = (const float*)d_in[6];
    const float* beta_p  = (const float*)d_in[7];
    float* out = (float*)d_out;

    setup_kernel<<<1, 256>>>(mu_p, alpha_p, beta_p);
    event_kernel<<<(BB * NN + 255) / 256, 256>>>(times, types, mask, t1);
    dim3 grid(NIT, NJT, BB);
    pair_kernel<<<grid, ITILE>>>(types);
    reduce_kernel<<<BB, 256>>>(mask, t0, t1, out);
}